// round 8
// baseline (speedup 1.0000x reference)
#include <cuda_runtime.h>
#include <cuda_bf16.h>
#include <math.h>

#define BATCH 1024
#define SEQ   512
#define HID   64
#define BC    16      // batch rows per CTA (full M=16 mma)
#define NT    512
#define HS    68      // padded h/x row stride (floats): conflict-free A-frag LDS
#define PS    264     // padded spre row stride
#define NCHUNK (BATCH / BC)   // 64 batch chunks

// Layer-0 hidden sequence: transport from layer-0 CTAs to layer-1 CTAs.
__device__ float g_h1[(size_t)BATCH * SEQ * HID];
// Per-chunk progress: number of steps layer 0 has published.
__device__ int g_prog[NCHUNK];

__global__ void init_flags() {
    if (threadIdx.x < NCHUNK) g_prog[threadIdx.x] = 0;
}

// RNA round fp32 -> tf32 bit pattern.
__device__ __forceinline__ unsigned tf32r(float f) {
    unsigned u; asm("cvt.rna.tf32.f32 %0, %1;" : "=r"(u) : "f"(f)); return u;
}

// Full m16n8k8 tf32 mma (all 16 A-rows live).
__device__ __forceinline__ void mma16(float* d,
                                      unsigned a0, unsigned a1,
                                      unsigned a2, unsigned a3,
                                      unsigned b0, unsigned b1) {
    asm volatile(
        "mma.sync.aligned.m16n8k8.row.col.f32.tf32.tf32.f32 "
        "{%0,%1,%2,%3}, {%4,%5,%6,%7}, {%8,%9}, {%0,%1,%2,%3};"
        : "+f"(d[0]), "+f"(d[1]), "+f"(d[2]), "+f"(d[3])
        : "r"(a0), "r"(a1), "r"(a2), "r"(a3), "r"(b0), "r"(b1));
}

__device__ __forceinline__ float sig_fast(float x) {
    return __fdividef(1.0f, 1.0f + __expf(-x));
}
__device__ __forceinline__ float tanh_fast(float x) {
    float e = __expf(-2.0f * fabsf(x));
    float t = __fdividef(1.0f - e, 1.0f + e);
    return copysignf(t, x);
}

// Acquire poll on a progress flag (CUTLASS-style strong load, L1-bypass).
__device__ __forceinline__ void wait_prog(const int* p, int need) {
    int v;
    do {
        asm volatile("ld.global.acquire.gpu.b32 %0, [%1];"
                     : "=r"(v) : "l"(p) : "memory");
    } while (v < need);
}

// Two-layer pipelined LSTM. grid=128: CTA<64 -> layer 0 (reads x, publishes
// h1 to g_h1 + progress flag), CTA>=64 -> layer 1 (consumes h1 lagged >=2
// steps, fused FC head). Per CTA: 16 batch rows, 512 threads.
// Publish protocol: every producer thread fences (drains its own STGs to the
// GPU coherence point) BEFORE the end-of-step barrier; thread 0 then stores
// the flag, which therefore physically follows all h1 writes of the step.
__global__ void __launch_bounds__(NT, 1) lstm2_kernel(
    const float* __restrict__ x,
    const float* __restrict__ wih0, const float* __restrict__ whh0,
    const float* __restrict__ bih0, const float* __restrict__ bhh0,
    const float* __restrict__ wih1, const float* __restrict__ whh1,
    const float* __restrict__ bih1, const float* __restrict__ bhh1,
    const float* __restrict__ fcw,  const float* __restrict__ fcb,
    float* __restrict__ out)
{
    __shared__ __align__(16) float sh[BC * HS];          // h_{t-1} (tf32 bits)
    __shared__ __align__(16) float sx[2][BC * HS];       // input_t (tf32), dbuf
    __shared__ __align__(16) float spre[2][BC * PS];     // split-K partials

    const int tid  = threadIdx.x;
    const int w    = tid >> 5, lane = tid & 31;
    const int grp  = lane >> 2, tg = lane & 3;
    const int wlo  = w & 7, kh = w >> 3;
    const int role  = (int)(blockIdx.x >> 6);     // 0: layer0, 1: layer1
    const int chunk = (int)(blockIdx.x & 63);
    const int b0    = chunk * BC;

    // P2 cells: (b, j) and (b+8, j).
    const int b = tid >> 6;        // 0..7
    const int j = tid & 63;

    const float* wih = role ? wih1 : wih0;
    const float* whh = role ? whh1 : whh0;
    const float* bih = role ? bih1 : bih0;
    const float* bhh = role ? bhh1 : bhh0;
    const float* in  = role ? (const float*)g_h1 : x;
    int* prog = &g_prog[chunk];

    // Weight fragments (once, tf32): kh=0 -> w_hh, kh=1 -> w_ih.
    const float* wsrc = kh ? wih : whh;
    unsigned bw[8][4][2];
#pragma unroll
    for (int kk = 0; kk < 8; kk++)
#pragma unroll
        for (int nn = 0; nn < 4; nn++)
#pragma unroll
            for (int hB = 0; hB < 2; hB++) {
                const int n = 32 * wlo + 8 * nn + grp;
                const int k = 8 * kk + tg + 4 * hB;
                bw[kk][nn][hB] = tf32r(wsrc[n * HID + k]);
            }

    // P2 biases (shared by both cells: same j).
    const float bi = bih[j]           + bhh[j];
    const float bf = bih[HID + j]     + bhh[HID + j];
    const float bg = bih[2 * HID + j] + bhh[2 * HID + j];
    const float bo = bih[3 * HID + j] + bhh[3 * HID + j];
    float c0 = 0.0f, c1 = 0.0f;

    // h = 0; stage input(t=0).  Consumer reads h1 L2-coherently (__ldcg).
    for (int i = tid; i < BC * HS; i += NT) sh[i] = 0.0f;
    if (role) wait_prog(prog, 1);
    sx[0][b * HS + j] = __uint_as_float(
        tf32r(__ldcg(&in[((size_t)(b0 + b) * SEQ) * HID + j])));
    sx[0][(b + 8) * HS + j] = __uint_as_float(
        tf32r(__ldcg(&in[((size_t)(b0 + b + 8) * SEQ) * HID + j])));
    __syncthreads();

    for (int t = 0; t < SEQ; t++) {
        const int cur = t & 1, nb = cur ^ 1;

        // ── mma phase: 4 independent accumulator chains of 8 HMMA.
        float d[4][4];
#pragma unroll
        for (int nn = 0; nn < 4; nn++)
#pragma unroll
            for (int i = 0; i < 4; i++) d[nn][i] = 0.0f;

        const float* asrc = kh ? &sx[cur][0] : sh;
#pragma unroll
        for (int kk = 0; kk < 8; kk++) {
            const unsigned a0 = __float_as_uint(asrc[grp * HS + 8 * kk + tg]);
            const unsigned a1 = __float_as_uint(asrc[(grp + 8) * HS + 8 * kk + tg]);
            const unsigned a2 = __float_as_uint(asrc[grp * HS + 8 * kk + tg + 4]);
            const unsigned a3 = __float_as_uint(asrc[(grp + 8) * HS + 8 * kk + tg + 4]);
#pragma unroll
            for (int nn = 0; nn < 4; nn++)
                mma16(d[nn], a0, a1, a2, a3, bw[kk][nn][0], bw[kk][nn][1]);
        }

        // ── prefetch input(t+1); consumer waits for publication first.
        float xp0 = 0.0f, xp1 = 0.0f;
        if (t + 1 < SEQ) {
            if (role) wait_prog(prog, t + 2);
            xp0 = __ldcg(&in[((size_t)(b0 + b) * SEQ + (t + 1)) * HID + j]);
            xp1 = __ldcg(&in[((size_t)(b0 + b + 8) * SEQ + (t + 1)) * HID + j]);
        }

        // ── store split-K partials.
#pragma unroll
        for (int nn = 0; nn < 4; nn++) {
            const int n0 = 32 * wlo + 8 * nn + 2 * tg;
            *(float2*)&spre[kh][grp * PS + n0]       = make_float2(d[nn][0], d[nn][1]);
            *(float2*)&spre[kh][(grp + 8) * PS + n0] = make_float2(d[nn][2], d[nn][3]);
        }
        __syncthreads();

        // ── P2: two cells per thread.
#pragma unroll
        for (int cc = 0; cc < 2; cc++) {
            const int bb = b + 8 * cc;
            const float pi = bi + spre[0][bb * PS + j]           + spre[1][bb * PS + j];
            const float pf = bf + spre[0][bb * PS + HID + j]     + spre[1][bb * PS + HID + j];
            const float pg = bg + spre[0][bb * PS + 2 * HID + j] + spre[1][bb * PS + 2 * HID + j];
            const float po = bo + spre[0][bb * PS + 3 * HID + j] + spre[1][bb * PS + 3 * HID + j];
            const float iv = sig_fast(pi);
            const float fv = sig_fast(pf);
            const float gv = tanh_fast(pg);
            const float ov = sig_fast(po);
            float& c = cc ? c1 : c0;
            c = fv * c + iv * gv;
            const float h = ov * tanh_fast(c);
            sh[bb * HS + j] = __uint_as_float(tf32r(h));
            if (role == 0)
                g_h1[((size_t)(b0 + bb) * SEQ + t) * HID + j] = h;
            if (t + 1 < SEQ)
                sx[nb][bb * HS + j] = __uint_as_float(tf32r(cc ? xp1 : xp0));
        }

        // ── producer: EVERY thread drains its own h1 STGs to the GPU
        // coherence point before arriving at the barrier. The flag store
        // below is then physically ordered after all h1 writes of step t.
        if (role == 0) __threadfence();
        __syncthreads();

        if (role == 0 && tid == 0)
            asm volatile("st.global.relaxed.gpu.b32 [%0], %1;"
                         :: "l"(prog), "r"(t + 1) : "memory");
    }

    // Fused FC head (layer-1 CTAs): warp w -> batch b0+w.
    if (role == 1) {
        float v = fcw[lane] * sh[w * HS + lane]
                + fcw[lane + 32] * sh[w * HS + lane + 32];
#pragma unroll
        for (int off = 16; off; off >>= 1)
            v += __shfl_down_sync(0xffffffffu, v, off);
        if (lane == 0) out[b0 + w] = v + fcb[0];
    }
}

extern "C" void kernel_launch(void* const* d_in, const int* in_sizes, int n_in,
                              void* d_out, int out_size)
{
    const float* x     = (const float*)d_in[0];
    const float* w_ih0 = (const float*)d_in[1];
    const float* w_hh0 = (const float*)d_in[2];
    const float* b_ih0 = (const float*)d_in[3];
    const float* b_hh0 = (const float*)d_in[4];
    const float* w_ih1 = (const float*)d_in[5];
    const float* w_hh1 = (const float*)d_in[6];
    const float* b_ih1 = (const float*)d_in[7];
    const float* b_hh1 = (const float*)d_in[8];
    const float* fc_w  = (const float*)d_in[9];
    const float* fc_b  = (const float*)d_in[10];
    float* out = (float*)d_out;

    init_flags<<<1, 64>>>();
    lstm2_kernel<<<2 * NCHUNK, NT>>>(x,
                                     w_ih0, w_hh0, b_ih0, b_hh0,
                                     w_ih1, w_hh1, b_ih1, b_hh1,
                                     fc_w, fc_b, out);
}

// round 9
// speedup vs baseline: 1.6199x; 1.6199x over previous
#include <cuda_runtime.h>
#include <cuda_bf16.h>
#include <math.h>

#define BATCH 1024
#define SEQ   512
#define HID   64
#define BC    16      // batch rows per CTA (full M=16 mma)
#define NT    512
#define HS    68      // padded h/x row stride (floats): conflict-free A-frag LDS
#define PS    264     // padded spre row stride
#define NCHUNK (BATCH / BC)   // 64 batch chunks
#define PUB   8       // publish granularity (steps)

// Layer-0 hidden sequence: transport from layer-0 CTAs to layer-1 CTAs.
__device__ float g_h1[(size_t)BATCH * SEQ * HID];
// Per-chunk progress: number of steps layer 0 has published.
__device__ int g_prog[NCHUNK];

__global__ void init_flags() {
    if (threadIdx.x < NCHUNK) g_prog[threadIdx.x] = 0;
}

// RNA round fp32 -> tf32 bit pattern.
__device__ __forceinline__ unsigned tf32r(float f) {
    unsigned u; asm("cvt.rna.tf32.f32 %0, %1;" : "=r"(u) : "f"(f)); return u;
}

// Full m16n8k8 tf32 mma (all 16 A-rows live).
__device__ __forceinline__ void mma16(float* d,
                                      unsigned a0, unsigned a1,
                                      unsigned a2, unsigned a3,
                                      unsigned b0, unsigned b1) {
    asm volatile(
        "mma.sync.aligned.m16n8k8.row.col.f32.tf32.tf32.f32 "
        "{%0,%1,%2,%3}, {%4,%5,%6,%7}, {%8,%9}, {%0,%1,%2,%3};"
        : "+f"(d[0]), "+f"(d[1]), "+f"(d[2]), "+f"(d[3])
        : "r"(a0), "r"(a1), "r"(a2), "r"(a3), "r"(b0), "r"(b1));
}

// Single-MUFU activations (MUFU.TANH). abs err ~2^-11, within budget on top
// of tf32 rounding (measured 4.8e-4 final with exact activations).
__device__ __forceinline__ float tanha(float x) {
    float r; asm("tanh.approx.f32 %0, %1;" : "=f"(r) : "f"(x)); return r;
}
__device__ __forceinline__ float sig_fast(float x) {
    return fmaf(tanha(0.5f * x), 0.5f, 0.5f);
}

// Acquire poll on a progress flag.
__device__ __forceinline__ void wait_prog(const int* p, int need) {
    int v;
    do {
        asm volatile("ld.global.acquire.gpu.b32 %0, [%1];"
                     : "=r"(v) : "l"(p) : "memory");
    } while (v < need);
}

// Two-layer pipelined LSTM. grid=128: CTA<64 -> layer 0 (reads x, publishes
// h1 + progress every PUB steps), CTA>=64 -> layer 1 (consumes h1 lagged
// ~PUB+1 steps, fused FC head). Per CTA: 16 batch rows, 512 threads.
__global__ void __launch_bounds__(NT, 1) lstm2_kernel(
    const float* __restrict__ x,
    const float* __restrict__ wih0, const float* __restrict__ whh0,
    const float* __restrict__ bih0, const float* __restrict__ bhh0,
    const float* __restrict__ wih1, const float* __restrict__ whh1,
    const float* __restrict__ bih1, const float* __restrict__ bhh1,
    const float* __restrict__ fcw,  const float* __restrict__ fcb,
    float* __restrict__ out)
{
    __shared__ __align__(16) float sh[BC * HS];          // h_{t-1} (tf32 bits)
    __shared__ __align__(16) float sx[2][BC * HS];       // input_t (tf32), dbuf
    __shared__ __align__(16) float spre[2][BC * PS];     // split-K partials

    const int tid  = threadIdx.x;
    const int w    = tid >> 5, lane = tid & 31;
    const int grp  = lane >> 2, tg = lane & 3;
    const int wlo  = w & 7, kh = w >> 3;
    const int role  = (int)(blockIdx.x >> 6);     // 0: layer0, 1: layer1
    const int chunk = (int)(blockIdx.x & 63);
    const int b0    = chunk * BC;

    // P2 cells: (b, j) and (b+8, j).
    const int b = tid >> 6;        // 0..7
    const int j = tid & 63;

    const float* wih = role ? wih1 : wih0;
    const float* whh = role ? whh1 : whh0;
    const float* bih = role ? bih1 : bih0;
    const float* bhh = role ? bhh1 : bhh0;
    const float* in  = role ? (const float*)g_h1 : x;
    int* prog = &g_prog[chunk];

    // Weight fragments (once, tf32): kh=0 -> w_hh, kh=1 -> w_ih.
    const float* wsrc = kh ? wih : whh;
    unsigned bw[8][4][2];
#pragma unroll
    for (int kk = 0; kk < 8; kk++)
#pragma unroll
        for (int nn = 0; nn < 4; nn++)
#pragma unroll
            for (int hB = 0; hB < 2; hB++) {
                const int n = 32 * wlo + 8 * nn + grp;
                const int k = 8 * kk + tg + 4 * hB;
                bw[kk][nn][hB] = tf32r(wsrc[n * HID + k]);
            }

    // P2 biases (shared by both cells: same j).
    const float bi = bih[j]           + bhh[j];
    const float bf = bih[HID + j]     + bhh[HID + j];
    const float bg = bih[2 * HID + j] + bhh[2 * HID + j];
    const float bo = bih[3 * HID + j] + bhh[3 * HID + j];
    float c0 = 0.0f, c1 = 0.0f;

    // h = 0; stage input(t=0). Consumer reads h1 L2-coherently (__ldcg).
    for (int i = tid; i < BC * HS; i += NT) sh[i] = 0.0f;
    if (role) wait_prog(prog, 1);
    sx[0][b * HS + j] = __uint_as_float(
        tf32r(__ldcg(&in[((size_t)(b0 + b) * SEQ) * HID + j])));
    sx[0][(b + 8) * HS + j] = __uint_as_float(
        tf32r(__ldcg(&in[((size_t)(b0 + b + 8) * SEQ) * HID + j])));
    __syncthreads();

    for (int t = 0; t < SEQ; t++) {
        const int cur = t & 1, nb = cur ^ 1;

        // ── consumer: one poll per PUB-step block covers all its prefetches.
        if (role && (t & (PUB - 1)) == 0) {
            int need = t + PUB + 1; if (need > SEQ) need = SEQ;
            wait_prog(prog, need);
        }

        // ── prefetch input(t+1) at top: LDG latency hides under mma phase.
        float xp0 = 0.0f, xp1 = 0.0f;
        if (t + 1 < SEQ) {
            xp0 = __ldcg(&in[((size_t)(b0 + b) * SEQ + (t + 1)) * HID + j]);
            xp1 = __ldcg(&in[((size_t)(b0 + b + 8) * SEQ + (t + 1)) * HID + j]);
        }

        // ── mma phase: 4 independent accumulator chains of 8 HMMA.
        float d[4][4];
#pragma unroll
        for (int nn = 0; nn < 4; nn++)
#pragma unroll
            for (int i = 0; i < 4; i++) d[nn][i] = 0.0f;

        const float* asrc = kh ? &sx[cur][0] : sh;
#pragma unroll
        for (int kk = 0; kk < 8; kk++) {
            const unsigned a0 = __float_as_uint(asrc[grp * HS + 8 * kk + tg]);
            const unsigned a1 = __float_as_uint(asrc[(grp + 8) * HS + 8 * kk + tg]);
            const unsigned a2 = __float_as_uint(asrc[grp * HS + 8 * kk + tg + 4]);
            const unsigned a3 = __float_as_uint(asrc[(grp + 8) * HS + 8 * kk + tg + 4]);
#pragma unroll
            for (int nn = 0; nn < 4; nn++)
                mma16(d[nn], a0, a1, a2, a3, bw[kk][nn][0], bw[kk][nn][1]);
        }

        // ── store split-K partials.
#pragma unroll
        for (int nn = 0; nn < 4; nn++) {
            const int n0 = 32 * wlo + 8 * nn + 2 * tg;
            *(float2*)&spre[kh][grp * PS + n0]       = make_float2(d[nn][0], d[nn][1]);
            *(float2*)&spre[kh][(grp + 8) * PS + n0] = make_float2(d[nn][2], d[nn][3]);
        }
        __syncthreads();

        // ── P2: two cells per thread (5 MUFU.TANH each).
#pragma unroll
        for (int cc = 0; cc < 2; cc++) {
            const int bb = b + 8 * cc;
            const float pi = bi + spre[0][bb * PS + j]           + spre[1][bb * PS + j];
            const float pf = bf + spre[0][bb * PS + HID + j]     + spre[1][bb * PS + HID + j];
            const float pg = bg + spre[0][bb * PS + 2 * HID + j] + spre[1][bb * PS + 2 * HID + j];
            const float po = bo + spre[0][bb * PS + 3 * HID + j] + spre[1][bb * PS + 3 * HID + j];
            const float iv = sig_fast(pi);
            const float fv = sig_fast(pf);
            const float gv = tanha(pg);
            const float ov = sig_fast(po);
            float& c = cc ? c1 : c0;
            c = fv * c + iv * gv;
            const float h = ov * tanha(c);
            sh[bb * HS + j] = __uint_as_float(tf32r(h));
            if (role == 0)
                g_h1[((size_t)(b0 + bb) * SEQ + t) * HID + j] = h;
            if (t + 1 < SEQ)
                sx[nb][bb * HS + j] = __uint_as_float(tf32r(cc ? xp1 : xp0));
        }

        // ── producer: publish every PUB steps. Each thread drains its own
        // STGs (gpu-scope fence) before the barrier; flag store after the
        // barrier is then ordered behind all h1 writes of the block.
        const bool pub = (role == 0) && (((t + 1) & (PUB - 1)) == 0);
        if (pub) __threadfence();
        __syncthreads();
        if (pub && tid == 0)
            asm volatile("st.global.relaxed.gpu.b32 [%0], %1;"
                         :: "l"(prog), "r"(t + 1) : "memory");
    }

    // Fused FC head (layer-1 CTAs): warp w -> batch b0+w.
    if (role == 1) {
        float v = fcw[lane] * sh[w * HS + lane]
                + fcw[lane + 32] * sh[w * HS + lane + 32];
#pragma unroll
        for (int off = 16; off; off >>= 1)
            v += __shfl_down_sync(0xffffffffu, v, off);
        if (lane == 0) out[b0 + w] = v + fcb[0];
    }
}

extern "C" void kernel_launch(void* const* d_in, const int* in_sizes, int n_in,
                              void* d_out, int out_size)
{
    const float* x     = (const float*)d_in[0];
    const float* w_ih0 = (const float*)d_in[1];
    const float* w_hh0 = (const float*)d_in[2];
    const float* b_ih0 = (const float*)d_in[3];
    const float* b_hh0 = (const float*)d_in[4];
    const float* w_ih1 = (const float*)d_in[5];
    const float* w_hh1 = (const float*)d_in[6];
    const float* b_ih1 = (const float*)d_in[7];
    const float* b_hh1 = (const float*)d_in[8];
    const float* fc_w  = (const float*)d_in[9];
    const float* fc_b  = (const float*)d_in[10];
    float* out = (float*)d_out;

    init_flags<<<1, 64>>>();
    lstm2_kernel<<<2 * NCHUNK, NT>>>(x,
                                     w_ih0, w_hh0, b_ih0, b_hh0,
                                     w_ih1, w_hh1, b_ih1, b_hh1,
                                     fc_w, fc_b, out);
}

// round 11
// speedup vs baseline: 1.9099x; 1.1790x over previous
#include <cuda_runtime.h>
#include <cuda_bf16.h>
#include <math.h>

#define BATCH 1024
#define SEQ   512
#define HID   64
#define BC    16
#define NT    512
#define HS    68              // padded h/x row stride (floats)
#define NCHUNK (BATCH / BC)   // 64
#define PUB   8

__device__ float g_h1[(size_t)BATCH * SEQ * HID];
__device__ int g_prog[NCHUNK];

__global__ void init_flags() {
    if (threadIdx.x < NCHUNK) g_prog[threadIdx.x] = 0;
}

__device__ __forceinline__ unsigned tf32r(float f) {
    unsigned u; asm("cvt.rna.tf32.f32 %0, %1;" : "=r"(u) : "f"(f)); return u;
}

__device__ __forceinline__ void mma16(float* d,
                                      unsigned a0, unsigned a1,
                                      unsigned a2, unsigned a3,
                                      unsigned b0, unsigned b1) {
    asm volatile(
        "mma.sync.aligned.m16n8k8.row.col.f32.tf32.tf32.f32 "
        "{%0,%1,%2,%3}, {%4,%5,%6,%7}, {%8,%9}, {%0,%1,%2,%3};"
        : "+f"(d[0]), "+f"(d[1]), "+f"(d[2]), "+f"(d[3])
        : "r"(a0), "r"(a1), "r"(a2), "r"(a3), "r"(b0), "r"(b1));
}

__device__ __forceinline__ float tanha(float x) {
    float r; asm("tanh.approx.f32 %0, %1;" : "=f"(r) : "f"(x)); return r;
}
__device__ __forceinline__ float sig_fast(float x) {
    return fmaf(tanha(0.5f * x), 0.5f, 0.5f);
}

__device__ __forceinline__ void wait_prog(const int* p, int need) {
    int v;
    do {
        asm volatile("ld.global.acquire.gpu.b32 %0, [%1];"
                     : "=r"(v) : "l"(p) : "memory");
    } while (v < need);
}

// Warp-specialized two-layer pipelined LSTM. grid=128: role 0 = layer 0
// (producer, publishes h1 every PUB steps), role 1 = layer 1 (consumer,
// fused FC head). Within each CTA (512 thr):
//   warps 0-7  ("R"): h(t) @ w_hh via mma (reads sh[cur]), register-resident
//                     cell update (gate-permuted B mapping puts i/f/g/o of
//                     the same cells in one thread), writes sh[nb] + g_h1.
//                     sh is DOUBLE-BUFFERED: the read set (all 64 cols) and
//                     write set (2 cols/thread) of different warps would
//                     otherwise race within the step (R10 bug).
//   warps 8-15 ("X"): x(t+1) @ w_ih via mma into sxp[nb]; stages x(t+2)
//                     into sx; consumer-side progress polling.
// One __syncthreads per step; all hand-offs double-buffered across it.
__global__ void __launch_bounds__(NT, 1) lstm2_kernel(
    const float* __restrict__ x,
    const float* __restrict__ wih0, const float* __restrict__ whh0,
    const float* __restrict__ bih0, const float* __restrict__ bhh0,
    const float* __restrict__ wih1, const float* __restrict__ whh1,
    const float* __restrict__ bih1, const float* __restrict__ bhh1,
    const float* __restrict__ fcw,  const float* __restrict__ fcb,
    float* __restrict__ out)
{
    __shared__ __align__(16) float sh[2][BC * HS];         // h, double-buffered
    __shared__ __align__(16) float sx[2][BC * HS];         // x_t (tf32), dbuf
    // x-GEMM fragment buffer: [buf][wlo][nn(gate)][row 0..15][col 0..7]
    __shared__ __align__(16) float sxp[2][8][4][16][8];

    const int tid  = threadIdx.x;
    const int w    = tid >> 5, lane = tid & 31;
    const int grp  = lane >> 2, tg = lane & 3;
    const int wlo  = w & 7;
    const bool isR = (w < 8);                 // recurrent/P2 group
    const int role  = (int)(blockIdx.x >> 6);
    const int chunk = (int)(blockIdx.x & 63);
    const int b0    = chunk * BC;

    // staging map (X warps): thread -> (batch row sb, 4 cols at sj)
    const int wt = tid & 255;
    const int sb = wt >> 4;
    const int sj = (wt & 15) * 4;

    const float* wih = role ? wih1 : wih0;
    const float* whh = role ? whh1 : whh0;
    const float* bih = role ? bih1 : bih0;
    const float* bhh = role ? bhh1 : bhh0;
    const float* in  = role ? (const float*)g_h1 : x;
    int* prog = &g_prog[chunk];

    // Gate-permuted weight fragments: tile nn == gate nn.
    // n_log = nn*64 + 8*wlo + grp ; k = 8*kk + tg (+4).
    const float* wsrc = isR ? whh : wih;
    unsigned bw[8][4][2];
#pragma unroll
    for (int kk = 0; kk < 8; kk++)
#pragma unroll
        for (int nn = 0; nn < 4; nn++) {
            const int n = nn * 64 + 8 * wlo + grp;
            bw[kk][nn][0] = tf32r(wsrc[n * HID + 8 * kk + tg]);
            bw[kk][nn][1] = tf32r(wsrc[n * HID + 8 * kk + tg + 4]);
        }

    // R-warp cell state & biases: cells (grp + 8rr, j0 + cc), j0 = 8wlo+2tg.
    const int j0 = 8 * wlo + 2 * tg;
    float bia[4][2];
#pragma unroll
    for (int g = 0; g < 4; g++) {
        bia[g][0] = bih[g * 64 + j0]     + bhh[g * 64 + j0];
        bia[g][1] = bih[g * 64 + j0 + 1] + bhh[g * 64 + j0 + 1];
    }
    float cst[2][2] = {{0.f, 0.f}, {0.f, 0.f}};

    // ── prologue: zero both h buffers, stage x(0), x(1); pre-GEMM x(0).
    for (int i = tid; i < 2 * BC * HS; i += NT) ((float*)sh)[i] = 0.0f;
    if (!isR) {
        if (role) wait_prog(prog, 2);
#pragma unroll
        for (int tt = 0; tt < 2; tt++) {
            const float4 v = *(const float4*)&in[((size_t)(b0 + sb) * SEQ + tt) * HID + sj];
            float4 r;
            r.x = __uint_as_float(tf32r(v.x));
            r.y = __uint_as_float(tf32r(v.y));
            r.z = __uint_as_float(tf32r(v.z));
            r.w = __uint_as_float(tf32r(v.w));
            *(float4*)&sx[tt][sb * HS + sj] = r;
        }
    }
    __syncthreads();

    // X-warp GEMM macro: sx[buf] @ w_ih -> sxp[buf].
#define XGEMM(buf)                                                            \
    {                                                                         \
        float d[4][4];                                                        \
        _Pragma("unroll")                                                     \
        for (int nn = 0; nn < 4; nn++)                                        \
            _Pragma("unroll")                                                 \
            for (int i = 0; i < 4; i++) d[nn][i] = 0.0f;                      \
        _Pragma("unroll")                                                     \
        for (int kk = 0; kk < 8; kk++) {                                      \
            const unsigned a0 = __float_as_uint(sx[buf][grp * HS + 8 * kk + tg]); \
            const unsigned a1 = __float_as_uint(sx[buf][(grp + 8) * HS + 8 * kk + tg]); \
            const unsigned a2 = __float_as_uint(sx[buf][grp * HS + 8 * kk + tg + 4]); \
            const unsigned a3 = __float_as_uint(sx[buf][(grp + 8) * HS + 8 * kk + tg + 4]); \
            _Pragma("unroll")                                                 \
            for (int nn = 0; nn < 4; nn++)                                    \
                mma16(d[nn], a0, a1, a2, a3, bw[kk][nn][0], bw[kk][nn][1]);   \
        }                                                                     \
        _Pragma("unroll")                                                     \
        for (int nn = 0; nn < 4; nn++) {                                      \
            *(float2*)&sxp[buf][wlo][nn][grp][2 * tg]     = make_float2(d[nn][0], d[nn][1]); \
            *(float2*)&sxp[buf][wlo][nn][grp + 8][2 * tg] = make_float2(d[nn][2], d[nn][3]); \
        }                                                                     \
    }

    if (!isR) XGEMM(0);
    __syncthreads();

    for (int t = 0; t < SEQ; t++) {
        const int cur = t & 1, nb = cur ^ 1;

        if (isR) {
            // ── R: init accumulators with x-partials, add h @ w_hh.
            float d[4][4];
#pragma unroll
            for (int nn = 0; nn < 4; nn++) {
                const float2 lo = *(const float2*)&sxp[cur][wlo][nn][grp][2 * tg];
                const float2 hi = *(const float2*)&sxp[cur][wlo][nn][grp + 8][2 * tg];
                d[nn][0] = lo.x; d[nn][1] = lo.y; d[nn][2] = hi.x; d[nn][3] = hi.y;
            }
#pragma unroll
            for (int kk = 0; kk < 8; kk++) {
                const unsigned a0 = __float_as_uint(sh[cur][grp * HS + 8 * kk + tg]);
                const unsigned a1 = __float_as_uint(sh[cur][(grp + 8) * HS + 8 * kk + tg]);
                const unsigned a2 = __float_as_uint(sh[cur][grp * HS + 8 * kk + tg + 4]);
                const unsigned a3 = __float_as_uint(sh[cur][(grp + 8) * HS + 8 * kk + tg + 4]);
#pragma unroll
                for (int nn = 0; nn < 4; nn++)
                    mma16(d[nn], a0, a1, a2, a3, bw[kk][nn][0], bw[kk][nn][1]);
            }
            // ── register-resident cell update: 4 cells/thread.
#pragma unroll
            for (int rr = 0; rr < 2; rr++) {
                float h2[2];
#pragma unroll
                for (int cc = 0; cc < 2; cc++) {
                    const int di = 2 * rr + cc;
                    const float iv = sig_fast(d[0][di] + bia[0][cc]);
                    const float fv = sig_fast(d[1][di] + bia[1][cc]);
                    const float gv = tanha(d[2][di] + bia[2][cc]);
                    const float ov = sig_fast(d[3][di] + bia[3][cc]);
                    float& cr = cst[rr][cc];
                    cr = fv * cr + iv * gv;
                    h2[cc] = ov * tanha(cr);
                }
                const int row = grp + 8 * rr;
                sh[nb][row * HS + j0]     = __uint_as_float(tf32r(h2[0]));
                sh[nb][row * HS + j0 + 1] = __uint_as_float(tf32r(h2[1]));
                if (role == 0)
                    *(float2*)&g_h1[((size_t)(b0 + row) * SEQ + t) * HID + j0] =
                        make_float2(h2[0], h2[1]);
            }
        } else {
            // ── X: poll (consumer), prefetch x(t+2), GEMM x(t+1), stage.
            if (role && (t & (PUB - 1)) == 0) {
                int need = t + PUB + 2; if (need > SEQ) need = SEQ;
                wait_prog(prog, need);
            }
            float4 v;
            if (t + 2 < SEQ)
                v = *(const float4*)&in[((size_t)(b0 + sb) * SEQ + (t + 2)) * HID + sj];
            if (t + 1 < SEQ) XGEMM(nb);
            if (t + 2 < SEQ) {
                float4 r;
                r.x = __uint_as_float(tf32r(v.x));
                r.y = __uint_as_float(tf32r(v.y));
                r.z = __uint_as_float(tf32r(v.z));
                r.w = __uint_as_float(tf32r(v.w));
                *(float4*)&sx[cur][sb * HS + sj] = r;
            }
        }

        // ── publish: R threads drain h1 STGs before the barrier.
        const bool pub = (role == 0) && (((t + 1) & (PUB - 1)) == 0);
        if (pub && isR) __threadfence();
        __syncthreads();
        if (pub && tid == 0)
            asm volatile("st.global.relaxed.gpu.b32 [%0], %1;"
                         :: "l"(prog), "r"(t + 1) : "memory");
    }

    // Fused FC head (layer-1 CTAs): final h is in sh[SEQ & 1] == sh[0].
    if (role == 1) {
        float v = fcw[lane] * sh[0][w * HS + lane]
                + fcw[lane + 32] * sh[0][w * HS + lane + 32];
#pragma unroll
        for (int off = 16; off; off >>= 1)
            v += __shfl_down_sync(0xffffffffu, v, off);
        if (lane == 0) out[b0 + w] = v + fcb[0];
    }
#undef XGEMM
}

extern "C" void kernel_launch(void* const* d_in, const int* in_sizes, int n_in,
                              void* d_out, int out_size)
{
    const float* x     = (const float*)d_in[0];
    const float* w_ih0 = (const float*)d_in[1];
    const float* w_hh0 = (const float*)d_in[2];
    const float* b_ih0 = (const float*)d_in[3];
    const float* b_hh0 = (const float*)d_in[4];
    const float* w_ih1 = (const float*)d_in[5];
    const float* w_hh1 = (const float*)d_in[6];
    const float* b_ih1 = (const float*)d_in[7];
    const float* b_hh1 = (const float*)d_in[8];
    const float* fc_w  = (const float*)d_in[9];
    const float* fc_b  = (const float*)d_in[10];
    float* out = (float*)d_out;

    init_flags<<<1, 64>>>();
    lstm2_kernel<<<2 * NCHUNK, NT>>>(x,
                                     w_ih0, w_hh0, b_ih0, b_hh0,
                                     w_ih1, w_hh1, b_ih1, b_hh1,
                                     fc_w, fc_b, out);
}

// round 12
// speedup vs baseline: 2.0670x; 1.0823x over previous
#include <cuda_runtime.h>
#include <cuda_fp16.h>
#include <math.h>

#define BATCH 1024
#define SEQ   512
#define HID   64
#define BC    16
#define NT    512
#define XS    72              // padded h/x row stride (halves): conflict-free
#define NCHUNK (BATCH / BC)   // 64
#define PUB   8

// Layer-0 hidden sequence, fp16 (halves transport bytes; layer 1 consumes raw).
__device__ __half g_h1[(size_t)BATCH * SEQ * HID];
__device__ int g_prog[NCHUNK];

__global__ void init_flags() {
    if (threadIdx.x < NCHUNK) g_prog[threadIdx.x] = 0;
}

__device__ __forceinline__ unsigned h2pack(float lo, float hi) {
    __half2 v = __floats2half2_rn(lo, hi);
    return reinterpret_cast<unsigned&>(v);
}

// m16n8k16 fp16 mma, fp32 accumulate.
__device__ __forceinline__ void mmah(float* d,
                                     unsigned a0, unsigned a1,
                                     unsigned a2, unsigned a3,
                                     unsigned b0, unsigned b1) {
    asm volatile(
        "mma.sync.aligned.m16n8k16.row.col.f32.f16.f16.f32 "
        "{%0,%1,%2,%3}, {%4,%5,%6,%7}, {%8,%9}, {%0,%1,%2,%3};"
        : "+f"(d[0]), "+f"(d[1]), "+f"(d[2]), "+f"(d[3])
        : "r"(a0), "r"(a1), "r"(a2), "r"(a3), "r"(b0), "r"(b1));
}

__device__ __forceinline__ float tanha(float x) {
    float r; asm("tanh.approx.f32 %0, %1;" : "=f"(r) : "f"(x)); return r;
}
__device__ __forceinline__ float sig_fast(float x) {
    return fmaf(tanha(0.5f * x), 0.5f, 0.5f);
}

__device__ __forceinline__ void wait_prog(const int* p, int need) {
    int v;
    do {
        asm volatile("ld.global.acquire.gpu.b32 %0, [%1];"
                     : "=r"(v) : "l"(p) : "memory");
    } while (v < need);
}

// Warp-specialized two-layer pipelined LSTM, fp16 tensor path.
// grid=128: role 0 = layer 0 (producer), role 1 = layer 1 (consumer + FC).
//   warps 0-7  ("R"): h(t) @ w_hh via m16n8k16 f16 mma (reads sh[cur]),
//                     register-resident cell update (gate-permuted B mapping),
//                     writes sh[nb] (fp16) + g_h1 (fp16).
//   warps 8-15 ("X"): x(t+1) @ w_ih -> sxp[nb] (f32 partials); stages x(t+2)
//                     into sx (fp16); consumer-side polling.
// One __syncthreads per step; all hand-offs double-buffered across it.
__global__ void __launch_bounds__(NT, 1) lstm2_kernel(
    const float* __restrict__ x,
    const float* __restrict__ wih0, const float* __restrict__ whh0,
    const float* __restrict__ bih0, const float* __restrict__ bhh0,
    const float* __restrict__ wih1, const float* __restrict__ whh1,
    const float* __restrict__ bih1, const float* __restrict__ bhh1,
    const float* __restrict__ fcw,  const float* __restrict__ fcb,
    float* __restrict__ out)
{
    __shared__ __align__(16) __half sh[2][BC * XS];        // h, double-buffered
    __shared__ __align__(16) __half sx[2][BC * XS];        // x_t, double-buffered
    // x-GEMM fp32 partials: [buf][wlo][nn(gate)][row 0..15][col 0..7]
    __shared__ __align__(16) float sxp[2][8][4][16][8];

    const int tid  = threadIdx.x;
    const int w    = tid >> 5, lane = tid & 31;
    const int grp  = lane >> 2, tg = lane & 3;
    const int wlo  = w & 7;
    const bool isR = (w < 8);
    const int role  = (int)(blockIdx.x >> 6);
    const int chunk = (int)(blockIdx.x & 63);
    const int b0    = chunk * BC;

    // staging map (X warps): thread -> (batch row sb, 4 cols at sj)
    const int wt = tid & 255;
    const int sb = wt >> 4;
    const int sj = (wt & 15) * 4;

    const float* wih = role ? wih1 : wih0;
    const float* whh = role ? whh1 : whh0;
    const float* bih = role ? bih1 : bih0;
    const float* bhh = role ? bhh1 : bhh0;
    int* prog = &g_prog[chunk];

    // Gate-permuted fp16 weight fragments: tile nn == gate nn.
    // n = nn*64 + 8*wlo + grp ; kstep kk covers k in [16kk, 16kk+16).
    // b0: k = 16kk+2tg, +1 ; b1: k = 16kk+2tg+8, +9.
    const float* wsrc = isR ? whh : wih;
    unsigned bw[4][4][2];
#pragma unroll
    for (int kk = 0; kk < 4; kk++)
#pragma unroll
        for (int nn = 0; nn < 4; nn++) {
            const int n = nn * 64 + 8 * wlo + grp;
            const int k0 = 16 * kk + 2 * tg;
            bw[kk][nn][0] = h2pack(wsrc[n * HID + k0],     wsrc[n * HID + k0 + 1]);
            bw[kk][nn][1] = h2pack(wsrc[n * HID + k0 + 8], wsrc[n * HID + k0 + 9]);
        }

    // R-warp cell state & biases: cells (grp + 8rr, j0 + cc), j0 = 8wlo+2tg.
    const int j0 = 8 * wlo + 2 * tg;
    float bia[4][2];
#pragma unroll
    for (int g = 0; g < 4; g++) {
        bia[g][0] = bih[g * 64 + j0]     + bhh[g * 64 + j0];
        bia[g][1] = bih[g * 64 + j0 + 1] + bhh[g * 64 + j0 + 1];
    }
    float cst[2][2] = {{0.f, 0.f}, {0.f, 0.f}};

    // ── prologue: zero both h buffers; stage x(0), x(1); pre-GEMM x(0).
    for (int i = tid; i < 2 * BC * XS / 2; i += NT) ((unsigned*)sh)[i] = 0u;
    if (!isR) {
        if (role) wait_prog(prog, 2);
#pragma unroll
        for (int tt = 0; tt < 2; tt++) {
            uint2 r;
            if (role == 0) {
                const float4 v = *(const float4*)&x[((size_t)(b0 + sb) * SEQ + tt) * HID + sj];
                r.x = h2pack(v.x, v.y);
                r.y = h2pack(v.z, v.w);
            } else {
                r = *(const uint2*)&g_h1[((size_t)(b0 + sb) * SEQ + tt) * HID + sj];
            }
            *(uint2*)&sx[tt][sb * XS + sj] = r;
        }
    }
    __syncthreads();

    // X-warp GEMM macro: sx[buf] @ w_ih -> sxp[buf] (4 HMMA chains of 4).
#define XGEMM(buf)                                                            \
    {                                                                         \
        float d[4][4];                                                        \
        _Pragma("unroll")                                                     \
        for (int nn = 0; nn < 4; nn++)                                        \
            _Pragma("unroll")                                                 \
            for (int i = 0; i < 4; i++) d[nn][i] = 0.0f;                      \
        _Pragma("unroll")                                                     \
        for (int kk = 0; kk < 4; kk++) {                                      \
            const int ko = 16 * kk + 2 * tg;                                  \
            const unsigned a0 = *(const unsigned*)&sx[buf][grp * XS + ko];    \
            const unsigned a1 = *(const unsigned*)&sx[buf][(grp + 8) * XS + ko]; \
            const unsigned a2 = *(const unsigned*)&sx[buf][grp * XS + ko + 8]; \
            const unsigned a3 = *(const unsigned*)&sx[buf][(grp + 8) * XS + ko + 8]; \
            _Pragma("unroll")                                                 \
            for (int nn = 0; nn < 4; nn++)                                    \
                mmah(d[nn], a0, a1, a2, a3, bw[kk][nn][0], bw[kk][nn][1]);    \
        }                                                                     \
        _Pragma("unroll")                                                     \
        for (int nn = 0; nn < 4; nn++) {                                      \
            *(float2*)&sxp[buf][wlo][nn][grp][2 * tg]     = make_float2(d[nn][0], d[nn][1]); \
            *(float2*)&sxp[buf][wlo][nn][grp + 8][2 * tg] = make_float2(d[nn][2], d[nn][3]); \
        }                                                                     \
    }

    if (!isR) XGEMM(0);
    __syncthreads();

    for (int t = 0; t < SEQ; t++) {
        const int cur = t & 1, nb = cur ^ 1;

        if (isR) {
            // ── R: init accumulators with x-partials, add h @ w_hh.
            float d[4][4];
#pragma unroll
            for (int nn = 0; nn < 4; nn++) {
                const float2 lo = *(const float2*)&sxp[cur][wlo][nn][grp][2 * tg];
                const float2 hi = *(const float2*)&sxp[cur][wlo][nn][grp + 8][2 * tg];
                d[nn][0] = lo.x; d[nn][1] = lo.y; d[nn][2] = hi.x; d[nn][3] = hi.y;
            }
#pragma unroll
            for (int kk = 0; kk < 4; kk++) {
                const int ko = 16 * kk + 2 * tg;
                const unsigned a0 = *(const unsigned*)&sh[cur][grp * XS + ko];
                const unsigned a1 = *(const unsigned*)&sh[cur][(grp + 8) * XS + ko];
                const unsigned a2 = *(const unsigned*)&sh[cur][grp * XS + ko + 8];
                const unsigned a3 = *(const unsigned*)&sh[cur][(grp + 8) * XS + ko + 8];
#pragma unroll
                for (int nn = 0; nn < 4; nn++)
                    mmah(d[nn], a0, a1, a2, a3, bw[kk][nn][0], bw[kk][nn][1]);
            }
            // ── register-resident cell update: 4 cells/thread.
#pragma unroll
            for (int rr = 0; rr < 2; rr++) {
                float h2[2];
#pragma unroll
                for (int cc = 0; cc < 2; cc++) {
                    const int di = 2 * rr + cc;
                    const float iv = sig_fast(d[0][di] + bia[0][cc]);
                    const float fv = sig_fast(d[1][di] + bia[1][cc]);
                    const float gv = tanha(d[2][di] + bia[2][cc]);
                    const float ov = sig_fast(d[3][di] + bia[3][cc]);
                    float& cr = cst[rr][cc];
                    cr = fv * cr + iv * gv;
                    h2[cc] = ov * tanha(cr);
                }
                const int row = grp + 8 * rr;
                const unsigned hp = h2pack(h2[0], h2[1]);
                *(unsigned*)&sh[nb][row * XS + j0] = hp;
                if (role == 0)
                    *(unsigned*)&g_h1[((size_t)(b0 + row) * SEQ + t) * HID + j0] = hp;
            }
        } else {
            // ── X: poll (consumer), prefetch x(t+2), GEMM x(t+1), stage.
            if (role && (t & (PUB - 1)) == 0) {
                int need = t + PUB + 2; if (need > SEQ) need = SEQ;
                wait_prog(prog, need);
            }
            uint2 r;
            if (t + 2 < SEQ) {
                if (role == 0) {
                    const float4 v = *(const float4*)&x[((size_t)(b0 + sb) * SEQ + (t + 2)) * HID + sj];
                    r.x = h2pack(v.x, v.y);
                    r.y = h2pack(v.z, v.w);
                } else {
                    r = *(const uint2*)&g_h1[((size_t)(b0 + sb) * SEQ + (t + 2)) * HID + sj];
                }
            }
            if (t + 1 < SEQ) XGEMM(nb);
            if (t + 2 < SEQ)
                *(uint2*)&sx[cur][sb * XS + sj] = r;
        }

        // ── publish: R threads drain h1 STGs before the barrier.
        const bool pub = (role == 0) && (((t + 1) & (PUB - 1)) == 0);
        if (pub && isR) __threadfence();
        __syncthreads();
        if (pub && tid == 0)
            asm volatile("st.global.relaxed.gpu.b32 [%0], %1;"
                         :: "l"(prog), "r"(t + 1) : "memory");
    }

    // Fused FC head (layer-1 CTAs): final h is in sh[0].
    if (role == 1) {
        float v = fcw[lane] * __half2float(sh[0][w * XS + lane])
                + fcw[lane + 32] * __half2float(sh[0][w * XS + lane + 32]);
#pragma unroll
        for (int off = 16; off; off >>= 1)
            v += __shfl_down_sync(0xffffffffu, v, off);
        if (lane == 0) out[b0 + w] = v + fcb[0];
    }
#undef XGEMM
}

extern "C" void kernel_launch(void* const* d_in, const int* in_sizes, int n_in,
                              void* d_out, int out_size)
{
    const float* x     = (const float*)d_in[0];
    const float* w_ih0 = (const float*)d_in[1];
    const float* w_hh0 = (const float*)d_in[2];
    const float* b_ih0 = (const float*)d_in[3];
    const float* b_hh0 = (const float*)d_in[4];
    const float* w_ih1 = (const float*)d_in[5];
    const float* w_hh1 = (const float*)d_in[6];
    const float* b_ih1 = (const float*)d_in[7];
    const float* b_hh1 = (const float*)d_in[8];
    const float* fc_w  = (const float*)d_in[9];
    const float* fc_b  = (const float*)d_in[10];
    float* out = (float*)d_out;

    init_flags<<<1, 64>>>();
    lstm2_kernel<<<2 * NCHUNK, NT>>>(x,
                                     w_ih0, w_hh0, b_ih0, b_hh0,
                                     w_ih1, w_hh1, b_ih1, b_hh1,
                                     fc_w, fc_b, out);
}